// round 12
// baseline (speedup 1.0000x reference)
#include <cuda_runtime.h>
#include <cuda_bf16.h>
#include <cstdint>

// Problem dims
#define TT 2048
#define BB 64
#define FFD 256
#define HH 256
#define NG 768  // 3*H

// Recurrence config: 16 clusters x 8 CTAs, 256 threads
#define CSZ 8
#define NCTA 128
#define NT 256

// Sentinel: NaN payload never produced by arithmetic or present in finite data
#define SENTL 0xFFC00001u
#define SENT64 0xFFC00001FFC00001ULL

// -------- device scratch --------
__device__ float g_xi[(size_t)TT * BB * NG];     // 2048*64*768
__device__ float g_dump[(size_t)TT * BB * HH];   // fallback ys sink

// -------- packed f32x2 helpers --------
__device__ __forceinline__ void ffma2(unsigned long long& d, unsigned long long a, unsigned long long b) {
    asm volatile("fma.rn.f32x2 %0, %1, %2, %0;" : "+l"(d) : "l"(a), "l"(b));
}
__device__ __forceinline__ unsigned long long dup2(float a) {
    unsigned long long d;
    asm("mov.b64 %0, {%1, %1};" : "=l"(d) : "f"(a));
    return d;
}
__device__ __forceinline__ unsigned long long pack2(float a, float b) {
    unsigned long long d;
    asm("mov.b64 %0, {%1, %2};" : "=l"(d) : "f"(a), "f"(b));
    return d;
}
__device__ __forceinline__ float2 unpack2(unsigned long long d) {
    float2 f;
    asm("mov.b64 {%0, %1}, %2;" : "=f"(f.x), "=f"(f.y) : "l"(d));
    return f;
}
__device__ __forceinline__ float tanh_ap(float x) {
    float y;
    asm("tanh.approx.f32 %0, %1;" : "=f"(y) : "f"(x));
    return y;
}
__device__ __forceinline__ float sigmoid_ap(float x) {
    return 0.5f * tanh_ap(0.5f * x) + 0.5f;
}
__device__ __forceinline__ uint32_t smem_u32(const void* p) {
    uint32_t a;
    asm("{ .reg .u64 t; cvta.to.shared.u64 t, %1; cvt.u32.u64 %0, t; }" : "=r"(a) : "l"(p));
    return a;
}
// Plain remote DSMEM 8B store — no fence, no tracking.
__device__ __forceinline__ void st_cluster_u64(uint32_t daddr, unsigned long long v) {
    asm volatile("st.shared::cluster.b64 [%0], %1;" :: "r"(daddr), "l"(v) : "memory");
}
// Volatile smem 8B load (poll)
__device__ __forceinline__ unsigned long long ldv64(const volatile unsigned long long* p) {
    return *p;
}

// ============================================================
// Kernel 1: xi = xs @ Wi   (M=131072, K=256, N=768) — FFMA2 tiled
// ============================================================
__global__ __launch_bounds__(256, 2) void gemm_xi_kernel(const float* __restrict__ A,
                                                         const float* __restrict__ W) {
    __shared__ float As[16][132];
    __shared__ float Bs[16][128];
    const int tid = threadIdx.x;
    const int m0 = blockIdx.y * 128;
    const int n0 = blockIdx.x * 128;
    const int nt = tid & 15;
    const int mt = tid >> 4;

    unsigned long long acc[8][4];
#pragma unroll
    for (int i = 0; i < 8; i++)
#pragma unroll
        for (int j = 0; j < 4; j++) acc[i][j] = 0ULL;

    for (int kt = 0; kt < 256; kt += 16) {
#pragma unroll
        for (int i = 0; i < 2; i++) {
            int f4 = tid + i * 256;
            int row = f4 >> 2;
            int kq = (f4 & 3) << 2;
            float4 v = *(const float4*)(A + (size_t)(m0 + row) * 256 + kt + kq);
            As[kq + 0][row] = v.x; As[kq + 1][row] = v.y;
            As[kq + 2][row] = v.z; As[kq + 3][row] = v.w;
        }
#pragma unroll
        for (int i = 0; i < 2; i++) {
            int f4 = tid + i * 256;
            int row = f4 >> 5;
            int nq = (f4 & 31) << 2;
            float4 v = *(const float4*)(W + (size_t)(kt + row) * 768 + n0 + nq);
            *(float4*)&Bs[row][nq] = v;
        }
        __syncthreads();
#pragma unroll
        for (int k = 0; k < 16; k++) {
            float4 a0 = *(const float4*)&As[k][mt * 8];
            float4 a1 = *(const float4*)&As[k][mt * 8 + 4];
            ulonglong2 bA = *(const ulonglong2*)&Bs[k][nt * 8];
            ulonglong2 bB = *(const ulonglong2*)&Bs[k][nt * 8 + 4];
            float av[8] = {a0.x, a0.y, a0.z, a0.w, a1.x, a1.y, a1.z, a1.w};
#pragma unroll
            for (int i = 0; i < 8; i++) {
                unsigned long long ad = dup2(av[i]);
                ffma2(acc[i][0], ad, bA.x);
                ffma2(acc[i][1], ad, bA.y);
                ffma2(acc[i][2], ad, bB.x);
                ffma2(acc[i][3], ad, bB.y);
            }
        }
        __syncthreads();
    }
#pragma unroll
    for (int i = 0; i < 8; i++) {
        float2 c0 = unpack2(acc[i][0]);
        float2 c1 = unpack2(acc[i][1]);
        float2 c2 = unpack2(acc[i][2]);
        float2 c3 = unpack2(acc[i][3]);
        size_t off = (size_t)(m0 + mt * 8 + i) * 768 + n0 + nt * 8;
        *(float4*)(g_xi + off)     = make_float4(c0.x, c0.y, c1.x, c1.y);
        *(float4*)(g_xi + off + 4) = make_float4(c2.x, c2.y, c3.x, c3.y);
    }
}

// ============================================================
// Kernel 2: clustered GRU recurrence — SENTINEL DATAFLOW (no rendezvous)
//  - h pre-duplicated f32x2 in sHT[2][256 k][4 b]
//  - producers: plain st.shared::cluster.b64 of dup2(h_new) to all 8 ranks
//  - consumers: poll each value inline in the GEMV (sentinel = NaN payload)
//  - receiver clears consumed buffer to sentinel BEFORE sending (dataflow-
//    ordered: any peer write transitively requires our sends -> our clear)
//  - NO mbarriers, NO cluster barriers, NO fences in the loop
// ============================================================

// smem float offsets
#define OFF_RED 0        // [256 threads][36]  partials
#define OFF_HT  9216     // [2][256 k][4 b] f32x2 dup'd = 4096 floats
#define SMEM_FLOATS 13312
#define SMEM_BYTES (SMEM_FLOATS * 4)   // 53248 > 48K default -> attr REQUIRED

__global__ __launch_bounds__(NT, 1) __cluster_dims__(CSZ, 1, 1)
void gru_rec_kernel(const float* __restrict__ c,
                    const float* __restrict__ Wh,
                    const float* __restrict__ bh,
                    const float* __restrict__ b_in,
                    float* __restrict__ ys,
                    float* __restrict__ finalc) {
    extern __shared__ float sm[];
    float* sRED = sm + OFF_RED;
    float* sHT  = sm + OFF_HT;   // slot (buf,k,b) at float off buf*2048 + (k*4+b)*2

    const int tid = threadIdx.x;
    uint32_t rank;
    asm("mov.u32 %0, %%cluster_ctarank;" : "=r"(rank));
    const int cid = blockIdx.x >> 3;          // cluster id 0..15 (batches 4cid..+3)

    // ---- phase-1 mapping + weight load into registers ----
    const int kc = tid >> 4;       // k-chunk 0..15 (16 k each)
    const int jp = tid & 15;       // j-pair 0..15 -> global j (rank*32 + 2jp, +1)
    const int j0w = (int)rank * 32 + jp * 2;

    unsigned long long wreg[48];   // [kk][g] f32x2 over j-pair
#pragma unroll
    for (int kk = 0; kk < 16; kk++) {
#pragma unroll
        for (int g = 0; g < 3; g++) {
            float2 w2 = __ldg((const float2*)(Wh + (size_t)(kc * 16 + kk) * 768 + g * 256 + j0w));
            wreg[kk * 3 + g] = pack2(w2.x, w2.y);
        }
    }

    // initial h (dup'd) into buf 0; buf 1 = sentinel
    for (int idx = tid; idx < 1024; idx += NT) {
        int k = idx >> 2;
        int b = idx & 3;
        float v = __ldg(c + (size_t)(cid * 4 + b) * 256 + k);
        *(unsigned long long*)&sHT[(k * 4 + b) * 2] = dup2(v);
        *(unsigned long long*)&sHT[2048 + (k * 4 + b) * 2] = SENT64;
    }

    // gate mapping (tid < 128): one (j, b) per thread
    const int jl = tid & 31;                     // j within rank slice
    const int b_g = (tid >> 5) & 3;              // batch 0..3
    const int j0 = (int)rank * 32 + jl;          // global j
    const int b_glob = cid * 4 + b_g;
    const int jpg = jl >> 1;                     // producer j-pair
    const int half = jl & 1;                     // lane within pair

    float bhr = 0.f, bhz = 0.f, bhn = 0.f, bin = 0.f;
    if (tid < 128) {
        bhr = __ldg(bh + j0);
        bhz = __ldg(bh + 256 + j0);
        bhn = __ldg(bh + 512 + j0);
        bin = __ldg(b_in + j0);
    }

    // remote sHT bases for all 8 ranks (includes self)
    uint32_t ht_local = smem_u32(sHT);
    uint32_t rdata[CSZ];
#pragma unroll
    for (int r = 0; r < CSZ; r++) {
        asm("mapa.shared::cluster.u32 %0, %1, %2;" : "=r"(rdata[r]) : "r"(ht_local), "r"(r));
    }

    __syncthreads();
    // ONE-TIME: all CTAs' buffers initialized before any remote traffic
    asm volatile("barrier.cluster.arrive.aligned;" ::: "memory");
    asm volatile("barrier.cluster.wait.aligned;" ::: "memory");

    // prefetch xi for t=0
    float xr = 0.f, xz = 0.f, xn = 0.f;
    if (tid < 128) {
        const float* xp = g_xi + (size_t)b_glob * 768 + j0;
        xr = __ldg(xp);
        xz = __ldg(xp + 256);
        xn = __ldg(xp + 512);
    }

    for (int t = 0; t < TT; t++) {
        const int p = t & 1;

        // -- phase 1: GEMV partials with inline sentinel polling --
        unsigned long long acc[3][4];
#pragma unroll
        for (int g = 0; g < 3; g++)
#pragma unroll
            for (int b = 0; b < 4; b++) acc[g][b] = 0ULL;
        {
            volatile unsigned long long* hb =
                (volatile unsigned long long*)(sHT + p * 2048) + kc * 64;  // 16 k x 4 slots
#pragma unroll
            for (int kk = 0; kk < 16; kk++) {
                unsigned long long h0 = hb[kk * 4 + 0];
                unsigned long long h1 = hb[kk * 4 + 1];
                unsigned long long h2 = hb[kk * 4 + 2];
                unsigned long long h3 = hb[kk * 4 + 3];
                while ((unsigned)h0 == SENTL) h0 = hb[kk * 4 + 0];
                while ((unsigned)h1 == SENTL) h1 = hb[kk * 4 + 1];
                while ((unsigned)h2 == SENTL) h2 = hb[kk * 4 + 2];
                while ((unsigned)h3 == SENTL) h3 = hb[kk * 4 + 3];
                unsigned long long w0 = wreg[kk * 3 + 0];
                unsigned long long w1 = wreg[kk * 3 + 1];
                unsigned long long w2 = wreg[kk * 3 + 2];
                ffma2(acc[0][0], w0, h0); ffma2(acc[0][1], w0, h1);
                ffma2(acc[0][2], w0, h2); ffma2(acc[0][3], w0, h3);
                ffma2(acc[1][0], w1, h0); ffma2(acc[1][1], w1, h1);
                ffma2(acc[1][2], w1, h2); ffma2(acc[1][3], w1, h3);
                ffma2(acc[2][0], w2, h0); ffma2(acc[2][1], w2, h1);
                ffma2(acc[2][2], w2, h2); ffma2(acc[2][3], w2, h3);
            }
        }
        // gate threads: poll + read h_old from buf[p]
        float h_old = 0.f;
        if (tid < 128) {
            volatile unsigned long long* hp =
                (volatile unsigned long long*)(sHT + p * 2048) + (j0 * 4 + b_g);
            unsigned long long hv = *hp;
            while ((unsigned)hv == SENTL) hv = *hp;
            h_old = __uint_as_float((unsigned)hv);
        }
        // write partials
        {
            float* rp = sRED + tid * 36;
#pragma unroll
            for (int b = 0; b < 4; b++) {
                ulonglong2 v;
                v.x = acc[0][b];
                v.y = acc[1][b];
                *(ulonglong2*)(rp + b * 8) = v;
                *(unsigned long long*)(rp + b * 8 + 4) = acc[2][b];
            }
        }
        __syncthreads();   // sync1: all reads of buf[p] complete

        // -- clear buf[p] to sentinel (all 256 threads, 4 slots each) --
        {
            ulonglong2 sv;
            sv.x = SENT64; sv.y = SENT64;
            ulonglong2* cp = (ulonglong2*)(sHT + p * 2048) + tid * 2;
            cp[0] = sv;
            cp[1] = sv;
        }
        // prefetch xi for t+1 while clearing
        float nxr = 0.f, nxz = 0.f, nxn = 0.f;
        if (tid < 128 && t + 1 < TT) {
            const float* xp = g_xi + ((size_t)(t + 1) * 64 + b_glob) * 768 + j0;
            nxr = __ldg(xp);
            nxz = __ldg(xp + 256);
            nxn = __ldg(xp + 512);
        }
        __syncthreads();   // sync2: clear visible before OUR sends (dataflow order)

        // -- reduce + gates + direct remote sends (128 threads) --
        if (tid < 128) {
            float hr = 0.f, hz = 0.f, hn = 0.f;
            const float* rp0 = sRED + jpg * 36 + b_g * 8 + half;
#pragma unroll
            for (int q = 0; q < 16; q++) {
                const float* pq = rp0 + q * (16 * 36);
                hr += pq[0];
                hz += pq[2];
                hn += pq[4];
            }
            float r = sigmoid_ap(xr + hr + bhr);
            float z = sigmoid_ap(xz + hz + bhz);
            float n = tanh_ap(xn + bin + r * (hn + bhn));
            float h_new = (1.0f - z) * n + z * h_old;

            ys[((size_t)t * 64 + b_glob) * 256 + j0] = h_new;
            if (t == TT - 1)
                finalc[(size_t)b_glob * 256 + j0] = h_new;

            if (t + 1 < TT) {
                unsigned long long hv = dup2(h_new);
                uint32_t off = (uint32_t)((p ^ 1) * 2048 + (j0 * 4 + b_g) * 2) * 4u;
#pragma unroll
                for (int r8 = 0; r8 < CSZ; r8++) {
                    st_cluster_u64(rdata[r8] + off, hv);
                }
            }
            // carry prefetched xi
            xr = nxr; xz = nxz; xn = nxn;
        }
        __syncthreads();   // sync3: sRED stable before next step's phase-1 overwrites
    }

    // no CTA exits while peers might still write its smem
    asm volatile("barrier.cluster.arrive.aligned;" ::: "memory");
    asm volatile("barrier.cluster.wait.aligned;" ::: "memory");
}

// ============================================================
extern "C" void kernel_launch(void* const* d_in, const int* in_sizes, int n_in,
                              void* d_out, int out_size) {
    const float* c    = (const float*)d_in[0];
    const float* xs   = (const float*)d_in[1];
    const float* Wi   = (const float*)d_in[2];
    const float* Wh   = (const float*)d_in[3];
    const float* bh   = (const float*)d_in[4];
    const float* b_in = (const float*)d_in[5];

    float* dmp;
    cudaGetSymbolAddress((void**)&dmp, g_dump);

    float* out = (float*)d_out;
    float* finalc;
    float* ys;
    const long long full = (long long)BB * HH + (long long)TT * BB * HH;
    if ((long long)out_size >= full) {
        finalc = out;            // tuple order: final_c first, then ys
        ys = out + BB * HH;
    } else if ((long long)out_size >= (long long)TT * BB * HH) {
        ys = out;
        finalc = dmp;
    } else {
        finalc = out;
        ys = dmp;
    }

    // REQUIRED: smem > 48KB default limit
    cudaFuncSetAttribute(gru_rec_kernel, cudaFuncAttributeMaxDynamicSharedMemorySize, SMEM_BYTES);

    // 1) xi = xs @ Wi
    dim3 ggrid(NG / 128, (TT * BB) / 128);
    gemm_xi_kernel<<<ggrid, 256>>>(xs, Wi);
    // 2) clustered recurrence (sentinel dataflow)
    gru_rec_kernel<<<NCTA, NT, SMEM_BYTES>>>(c, Wh, bh, b_in, ys, finalc);
}

// round 13
// speedup vs baseline: 1.6696x; 1.6696x over previous
#include <cuda_runtime.h>
#include <cuda_bf16.h>
#include <cstdint>

// Problem dims
#define TT 2048
#define BB 64
#define FFD 256
#define HH 256
#define NG 768  // 3*H

// Recurrence config: 16 clusters x 8 CTAs, 256 threads
#define CSZ 8
#define NCTA 128
#define NT 256

// -------- device scratch --------
__device__ float g_xi[(size_t)TT * BB * NG];     // 2048*64*768
__device__ float g_dump[(size_t)TT * BB * HH];   // fallback ys sink

// -------- packed f32x2 helpers --------
__device__ __forceinline__ void ffma2(unsigned long long& d, unsigned long long a, unsigned long long b) {
    asm volatile("fma.rn.f32x2 %0, %1, %2, %0;" : "+l"(d) : "l"(a), "l"(b));
}
__device__ __forceinline__ unsigned long long dup2(float a) {
    unsigned long long d;
    asm("mov.b64 %0, {%1, %1};" : "=l"(d) : "f"(a));
    return d;
}
__device__ __forceinline__ unsigned long long pack2(float a, float b) {
    unsigned long long d;
    asm("mov.b64 %0, {%1, %2};" : "=l"(d) : "f"(a), "f"(b));
    return d;
}
__device__ __forceinline__ float2 unpack2(unsigned long long d) {
    float2 f;
    asm("mov.b64 {%0, %1}, %2;" : "=f"(f.x), "=f"(f.y) : "l"(d));
    return f;
}
__device__ __forceinline__ float tanh_ap(float x) {
    float y;
    asm("tanh.approx.f32 %0, %1;" : "=f"(y) : "f"(x));
    return y;
}
__device__ __forceinline__ float sigmoid_ap(float x) {
    return 0.5f * tanh_ap(0.5f * x) + 0.5f;
}
__device__ __forceinline__ uint32_t smem_u32(const void* p) {
    uint32_t a;
    asm("{ .reg .u64 t; cvta.to.shared.u64 t, %1; cvt.u32.u64 %0, t; }" : "=r"(a) : "l"(p));
    return a;
}
// CTA-scope wait: no cluster-scope acquire -> no CCTL.IVALL on the poll loop.
__device__ __forceinline__ void mbar_wait_cta(uint32_t mbar, unsigned parity) {
    asm volatile(
        "{\n\t.reg .pred p;\n\t"
        "WAIT_%=:\n\t"
        "mbarrier.try_wait.parity.acquire.cta.shared::cta.b64 p, [%0], %1, 0x989680;\n\t"
        "@!p bra WAIT_%=;\n\t}"
        :: "r"(mbar), "r"(parity) : "memory");
}
// Remote tx-tracked 8B store (dup'd f32 pair) to peer CTA smem + chunk mbarrier.
__device__ __forceinline__ void st_async_u64(uint32_t daddr, unsigned long long v, uint32_t maddr) {
    asm volatile(
        "st.async.shared::cluster.mbarrier::complete_tx::bytes.b64 [%0], %1, [%2];"
        :: "r"(daddr), "l"(v), "r"(maddr) : "memory");
}

// ============================================================
// Kernel 1: xi = xs @ Wi   (M=131072, K=256, N=768) — FFMA2 tiled
// ============================================================
__global__ __launch_bounds__(256, 2) void gemm_xi_kernel(const float* __restrict__ A,
                                                         const float* __restrict__ W) {
    __shared__ float As[16][132];
    __shared__ float Bs[16][128];
    const int tid = threadIdx.x;
    const int m0 = blockIdx.y * 128;
    const int n0 = blockIdx.x * 128;
    const int nt = tid & 15;
    const int mt = tid >> 4;

    unsigned long long acc[8][4];
#pragma unroll
    for (int i = 0; i < 8; i++)
#pragma unroll
        for (int j = 0; j < 4; j++) acc[i][j] = 0ULL;

    for (int kt = 0; kt < 256; kt += 16) {
#pragma unroll
        for (int i = 0; i < 2; i++) {
            int f4 = tid + i * 256;
            int row = f4 >> 2;
            int kq = (f4 & 3) << 2;
            float4 v = *(const float4*)(A + (size_t)(m0 + row) * 256 + kt + kq);
            As[kq + 0][row] = v.x; As[kq + 1][row] = v.y;
            As[kq + 2][row] = v.z; As[kq + 3][row] = v.w;
        }
#pragma unroll
        for (int i = 0; i < 2; i++) {
            int f4 = tid + i * 256;
            int row = f4 >> 5;
            int nq = (f4 & 31) << 2;
            float4 v = *(const float4*)(W + (size_t)(kt + row) * 768 + n0 + nq);
            *(float4*)&Bs[row][nq] = v;
        }
        __syncthreads();
#pragma unroll
        for (int k = 0; k < 16; k++) {
            float4 a0 = *(const float4*)&As[k][mt * 8];
            float4 a1 = *(const float4*)&As[k][mt * 8 + 4];
            ulonglong2 bA = *(const ulonglong2*)&Bs[k][nt * 8];
            ulonglong2 bB = *(const ulonglong2*)&Bs[k][nt * 8 + 4];
            float av[8] = {a0.x, a0.y, a0.z, a0.w, a1.x, a1.y, a1.z, a1.w};
#pragma unroll
            for (int i = 0; i < 8; i++) {
                unsigned long long ad = dup2(av[i]);
                ffma2(acc[i][0], ad, bA.x);
                ffma2(acc[i][1], ad, bA.y);
                ffma2(acc[i][2], ad, bB.x);
                ffma2(acc[i][3], ad, bB.y);
            }
        }
        __syncthreads();
    }
#pragma unroll
    for (int i = 0; i < 8; i++) {
        float2 c0 = unpack2(acc[i][0]);
        float2 c1 = unpack2(acc[i][1]);
        float2 c2 = unpack2(acc[i][2]);
        float2 c3 = unpack2(acc[i][3]);
        size_t off = (size_t)(m0 + mt * 8 + i) * 768 + n0 + nt * 8;
        *(float4*)(g_xi + off)     = make_float4(c0.x, c0.y, c1.x, c1.y);
        *(float4*)(g_xi + off + 4) = make_float4(c2.x, c2.y, c3.x, c3.y);
    }
}

// ============================================================
// Kernel 2: clustered GRU recurrence — PER-CHUNK MBARRIERS (pipelined arrival)
//  - 16 k-chunk mbarriers per buffer; chunk q produced solely by rank q>>1
//  - phase-1 thread waits ONLY its own chunk (acquire.cta try_wait)
//  - gate threads st.async.b64 dup'd h_new to all 8 ranks, complete_tx on
//    the destination chunk mbarrier (512B per chunk per step)
//  - no global per-step rendezvous anywhere
// ============================================================

// smem float offsets
#define OFF_RED 0        // [256 threads][36] partials
#define OFF_HT  9216     // [2][256 k][4 b] f32x2 dup'd = 4096 floats
#define OFF_MB  13312    // 32 mbarriers (2 bufs x 16 chunks) = 64 floats
#define SMEM_FLOATS 13376
#define SMEM_BYTES (SMEM_FLOATS * 4)   // 53504 > 48K -> attr REQUIRED

#define CH_TX 512u       // per-chunk bytes: 16 j x 4 b x 8B from one source rank

__global__ __launch_bounds__(NT, 1) __cluster_dims__(CSZ, 1, 1)
void gru_rec_kernel(const float* __restrict__ c,
                    const float* __restrict__ Wh,
                    const float* __restrict__ bh,
                    const float* __restrict__ b_in,
                    float* __restrict__ ys,
                    float* __restrict__ finalc) {
    extern __shared__ float sm[];
    float* sRED = sm + OFF_RED;
    float* sHT  = sm + OFF_HT;   // slot (buf,k,b) at float off buf*2048 + (k*4+b)*2

    const int tid = threadIdx.x;
    uint32_t rank;
    asm("mov.u32 %0, %%cluster_ctarank;" : "=r"(rank));
    const int cid = blockIdx.x >> 3;          // cluster id 0..15 (batches 4cid..+3)

    const uint32_t mbase = smem_u32(sm + OFF_MB);   // mb[buf][q] at mbase + (buf*16+q)*8

    // ---- init 32 mbarriers (count = 1: the expect_tx arrival) ----
    if (tid == 0) {
#pragma unroll
        for (int i = 0; i < 32; i++) {
            asm volatile("mbarrier.init.shared.b64 [%0], %1;" :: "r"(mbase + i * 8u), "r"(1u) : "memory");
        }
        // arm buf1 chunks for step-0 sends (which target buf 1)
#pragma unroll
        for (int q = 0; q < 16; q++) {
            asm volatile("mbarrier.arrive.expect_tx.shared.b64 _, [%0], %1;"
                         :: "r"(mbase + (16u + (uint32_t)q) * 8u), "r"(CH_TX) : "memory");
        }
    }

    // ---- phase-1 mapping + weight load into registers ----
    const int kc = tid >> 4;       // k-chunk 0..15 (16 k each)
    const int jp = tid & 15;       // j-pair 0..15 -> global j (rank*32 + 2jp, +1)
    const int j0w = (int)rank * 32 + jp * 2;

    unsigned long long wreg[48];   // [kk][g] f32x2 over j-pair
#pragma unroll
    for (int kk = 0; kk < 16; kk++) {
#pragma unroll
        for (int g = 0; g < 3; g++) {
            float2 w2 = __ldg((const float2*)(Wh + (size_t)(kc * 16 + kk) * 768 + g * 256 + j0w));
            wreg[kk * 3 + g] = pack2(w2.x, w2.y);
        }
    }

    // initial h (dup'd) into buf 0
    for (int idx = tid; idx < 1024; idx += NT) {
        int k = idx >> 2;
        int b = idx & 3;
        float v = __ldg(c + (size_t)(cid * 4 + b) * 256 + k);
        *(unsigned long long*)&sHT[(k * 4 + b) * 2] = dup2(v);
    }

    // gate mapping (tid < 128): one (j, b) per thread
    const int jl = tid & 31;                     // j within rank slice
    const int b_g = (tid >> 5) & 3;              // batch 0..3
    const int j0 = (int)rank * 32 + jl;          // global j
    const int b_glob = cid * 4 + b_g;
    const int jpg = jl >> 1;                     // producer j-pair
    const int half = jl & 1;                     // lane within pair
    const int chq = j0 >> 4;                     // destination chunk (2*rank or 2*rank+1)

    float bhr = 0.f, bhz = 0.f, bhn = 0.f, bin = 0.f;
    if (tid < 128) {
        bhr = __ldg(bh + j0);
        bhz = __ldg(bh + 256 + j0);
        bhn = __ldg(bh + 512 + j0);
        bin = __ldg(b_in + j0);
    }

    // remote bases for all 8 ranks
    uint32_t ht_local = smem_u32(sHT);
    uint32_t rdata[CSZ], rmb[CSZ];
#pragma unroll
    for (int r = 0; r < CSZ; r++) {
        asm("mapa.shared::cluster.u32 %0, %1, %2;" : "=r"(rdata[r]) : "r"(ht_local), "r"(r));
        asm("mapa.shared::cluster.u32 %0, %1, %2;" : "=r"(rmb[r]) : "r"(mbase), "r"(r));
    }

    __syncthreads();
    // ONE-TIME: mbarriers + buf0 ready everywhere before any remote traffic
    asm volatile("barrier.cluster.arrive.aligned;" ::: "memory");
    asm volatile("barrier.cluster.wait.aligned;" ::: "memory");

    // prefetch xi for t=0
    float xr = 0.f, xz = 0.f, xn = 0.f;
    if (tid < 128) {
        const float* xp = g_xi + (size_t)b_glob * 768 + j0;
        xr = __ldg(xp);
        xz = __ldg(xp + 256);
        xn = __ldg(xp + 512);
    }

    unsigned ph0 = 0, ph1 = 0;   // per-thread parity for my chunk on buf0/buf1
    for (int t = 0; t < TT; t++) {
        const int p = t & 1;

        // -- wait for MY chunk only (skip t=0: buf0 pre-filled) --
        if (t > 0) {
            uint32_t mb = mbase + (uint32_t)(p * 16 + kc) * 8u;
            if (p) { mbar_wait_cta(mb, ph1); ph1 ^= 1; }
            else   { mbar_wait_cta(mb, ph0); ph0 ^= 1; }
        }

        // -- phase 1: register-weight GEMV partials (dup'd h, no MOVs) --
        unsigned long long acc[3][4];
#pragma unroll
        for (int g = 0; g < 3; g++)
#pragma unroll
            for (int b = 0; b < 4; b++) acc[g][b] = 0ULL;
        {
            const float* hb = sHT + p * 2048 + kc * 128;  // 16 k rows x 32B
#pragma unroll
            for (int kk = 0; kk < 16; kk++) {
                ulonglong2 hA = *(const ulonglong2*)(hb + kk * 8);      // dup(b0), dup(b1)
                ulonglong2 hB = *(const ulonglong2*)(hb + kk * 8 + 4);  // dup(b2), dup(b3)
                unsigned long long w0 = wreg[kk * 3 + 0];
                unsigned long long w1 = wreg[kk * 3 + 1];
                unsigned long long w2 = wreg[kk * 3 + 2];
                ffma2(acc[0][0], w0, hA.x); ffma2(acc[0][1], w0, hA.y);
                ffma2(acc[0][2], w0, hB.x); ffma2(acc[0][3], w0, hB.y);
                ffma2(acc[1][0], w1, hA.x); ffma2(acc[1][1], w1, hA.y);
                ffma2(acc[1][2], w1, hB.x); ffma2(acc[1][3], w1, hB.y);
                ffma2(acc[2][0], w2, hA.x); ffma2(acc[2][1], w2, hA.y);
                ffma2(acc[2][2], w2, hB.x); ffma2(acc[2][3], w2, hB.y);
            }
        }
        // write partials: per b: [j0g0,j1g0, j0g1,j1g1, j0g2,j1g2]
        {
            float* rp = sRED + tid * 36;
#pragma unroll
            for (int b = 0; b < 4; b++) {
                ulonglong2 v;
                v.x = acc[0][b];
                v.y = acc[1][b];
                *(ulonglong2*)(rp + b * 8) = v;
                *(unsigned long long*)(rp + b * 8 + 4) = acc[2][b];
            }
        }
        __syncthreads();   // sync1: all chunk phases flipped; sRED complete

        // re-arm buf p's chunk mbarriers for their next fill (sends at t+1)
        if (tid >= 128 && tid < 144 && t + 2 < TT) {
            uint32_t mb = mbase + (uint32_t)(p * 16 + (tid - 128)) * 8u;
            asm volatile("mbarrier.arrive.expect_tx.shared.b64 _, [%0], %1;"
                         :: "r"(mb), "r"(CH_TX) : "memory");
        }

        // -- phase 2+3: reduce + gates + direct sends (128 threads) --
        if (tid < 128) {
            float hr = 0.f, hz = 0.f, hn = 0.f;
            const float* rp0 = sRED + jpg * 36 + b_g * 8 + half;
#pragma unroll
            for (int q = 0; q < 16; q++) {
                const float* pq = rp0 + q * (16 * 36);
                hr += pq[0];
                hz += pq[2];
                hn += pq[4];
            }
            float h_old = sHT[p * 2048 + (j0 * 4 + b_g) * 2];
            float r = sigmoid_ap(xr + hr + bhr);
            float z = sigmoid_ap(xz + hz + bhz);
            float n = tanh_ap(xn + bin + r * (hn + bhn));
            float h_new = (1.0f - z) * n + z * h_old;

            ys[((size_t)t * 64 + b_glob) * 256 + j0] = h_new;
            if (t == TT - 1)
                finalc[(size_t)b_glob * 256 + j0] = h_new;

            if (t + 1 < TT) {
                unsigned long long hv = dup2(h_new);
                const int nxt = p ^ 1;
                uint32_t doff = (uint32_t)(nxt * 2048 + (j0 * 4 + b_g) * 2) * 4u;
                uint32_t moff = (uint32_t)(nxt * 16 + chq) * 8u;
#pragma unroll
                for (int r8 = 0; r8 < CSZ; r8++) {
                    st_async_u64(rdata[r8] + doff, hv, rmb[r8] + moff);
                }
            }
            // prefetch xi for t+1
            if (t + 1 < TT) {
                const float* xp = g_xi + ((size_t)(t + 1) * 64 + b_glob) * 768 + j0;
                xr = __ldg(xp);
                xz = __ldg(xp + 256);
                xn = __ldg(xp + 512);
            }
        }
        __syncthreads();   // sync2: sRED stable before next step's phase-1 overwrites
    }

    // no CTA exits while peers might still write its smem
    asm volatile("barrier.cluster.arrive.aligned;" ::: "memory");
    asm volatile("barrier.cluster.wait.aligned;" ::: "memory");
}

// ============================================================
extern "C" void kernel_launch(void* const* d_in, const int* in_sizes, int n_in,
                              void* d_out, int out_size) {
    const float* c    = (const float*)d_in[0];
    const float* xs   = (const float*)d_in[1];
    const float* Wi   = (const float*)d_in[2];
    const float* Wh   = (const float*)d_in[3];
    const float* bh   = (const float*)d_in[4];
    const float* b_in = (const float*)d_in[5];

    float* dmp;
    cudaGetSymbolAddress((void**)&dmp, g_dump);

    float* out = (float*)d_out;
    float* finalc;
    float* ys;
    const long long full = (long long)BB * HH + (long long)TT * BB * HH;
    if ((long long)out_size >= full) {
        finalc = out;            // tuple order: final_c first, then ys
        ys = out + BB * HH;
    } else if ((long long)out_size >= (long long)TT * BB * HH) {
        ys = out;
        finalc = dmp;
    } else {
        finalc = out;
        ys = dmp;
    }

    // REQUIRED: smem > 48KB default limit
    cudaFuncSetAttribute(gru_rec_kernel, cudaFuncAttributeMaxDynamicSharedMemorySize, SMEM_BYTES);

    // 1) xi = xs @ Wi
    dim3 ggrid(NG / 128, (TT * BB) / 128);
    gemm_xi_kernel<<<ggrid, 256>>>(xs, Wi);
    // 2) clustered recurrence (per-chunk mbarrier pipelined arrival)
    gru_rec_kernel<<<NCTA, NT, SMEM_BYTES>>>(c, Wh, bh, b_in, ys, finalc);
}